// round 11
// baseline (speedup 1.0000x reference)
#include <cuda_runtime.h>
#include <cuda_fp16.h>

#define N_NODES 50000
#define N_PAD   50048
#define N_EDGES 800000
#define CIN 128
#define COUT 128

#define SCAN_BLOCKS ((N_NODES + 255) / 256)   // 196
#define NBLK 592                              // 148 SMs x 4 blocks (co-resident)

// Scratch (allocation-free: __device__ globals)
__device__ int      g_is64;
__device__ int      g_deg[N_NODES];
__device__ int      g_off[N_NODES + 1];
__device__ int      g_cur[N_NODES];
__device__ unsigned long long g_state[SCAN_BLOCKS];
__device__ unsigned g_barA, g_barB, g_barC;
__device__ int      g_tscan;
__device__ int      g_scol[N_EDGES];
__device__ __half   g_xh[(size_t)N_PAD * CIN];
__device__ __half   g_Wh[COUT * CIN];
__device__ __half   g_xt[(size_t)N_NODES * COUT];

// ---------------------------------------------------------------------------
__device__ __forceinline__ void ldsm_x4(unsigned* r, unsigned addr) {
    asm volatile("ldmatrix.sync.aligned.m8n8.x4.shared.b16 {%0,%1,%2,%3}, [%4];"
                 : "=r"(r[0]), "=r"(r[1]), "=r"(r[2]), "=r"(r[3]) : "r"(addr));
}
__device__ __forceinline__ void mma16816(float* c, const unsigned* a, const unsigned* b) {
    asm volatile(
        "mma.sync.aligned.m16n8k16.row.col.f32.f16.f16.f32 "
        "{%0,%1,%2,%3}, {%4,%5,%6,%7}, {%8,%9}, {%0,%1,%2,%3};"
        : "+f"(c[0]), "+f"(c[1]), "+f"(c[2]), "+f"(c[3])
        : "r"(a[0]), "r"(a[1]), "r"(a[2]), "r"(a[3]), "r"(b[0]), "r"(b[1]));
}
__device__ __forceinline__ void cp16(unsigned dst, const void* src) {
    asm volatile("cp.async.cg.shared.global [%0], [%1], 16;" :: "r"(dst), "l"(src));
}

__device__ __forceinline__ void grid_barrier(unsigned* ctr) {
    __syncthreads();
    if (threadIdx.x == 0) {
        __threadfence();
        atomicAdd(ctr, 1u);
        while (atomicAdd(ctr, 0u) < NBLK) __nanosleep(64);
    }
    __syncthreads();
}

// ---------------------------------------------------------------------------
// K_CSR: persistent kernel — init + count + scan + scatter with grid barriers.
__global__ void __launch_bounds__(256, 4) k_csr(const void* __restrict__ ei) {
    int tid = threadIdx.x;
    int gthread = blockIdx.x * 256 + tid;
    const int gsize = NBLK * 256;

    // ---- P0: init ----
    for (int i = gthread; i < N_NODES; i += gsize) g_deg[i] = 0;
    if (gthread < SCAN_BLOCKS) g_state[gthread] = 0ull;
    if (blockIdx.x == 0) {
        if (tid == 0) { g_barB = 0; g_barC = 0; g_tscan = 0; }
        if (tid < 32) {
            const long long* p = (const long long*)ei;
            long long v0 = p[tid];
            long long v1 = p[tid + 32];
            int bad = (v0 < 0 || v0 >= N_NODES || v1 < 0 || v1 >= N_NODES);
            unsigned m = __ballot_sync(0xffffffffu, bad);
            if (tid == 0) g_is64 = (m == 0);
        }
    }
    grid_barrier(&g_barA);

    // ---- P1: count ----
    int is64 = g_is64;
    if (is64) {
        const longlong2* p = (const longlong2*)ei;      // rows: 400000 x 16B
        for (int i = gthread; i < N_EDGES / 2; i += gsize) {
            longlong2 v = p[i];
            int r0 = (int)v.x, r1 = (int)v.y;
            if ((unsigned)r0 < N_NODES) atomicAdd(&g_deg[r0], 1);
            if ((unsigned)r1 < N_NODES) atomicAdd(&g_deg[r1], 1);
        }
    } else {
        const int* p = (const int*)ei;
        for (int e = gthread; e < N_EDGES; e += gsize) {
            int r = p[e];
            if ((unsigned)r < N_NODES) atomicAdd(&g_deg[r], 1);
        }
    }
    grid_barrier(&g_barB);
    if (blockIdx.x == 0 && tid == 0) g_barA = 0;    // all A-arrivals long done

    // ---- P2: decoupled-lookback scan over ticketed tiles ----
    __shared__ int sv[256];
    __shared__ int stile, sexcl;
    while (true) {
        if (tid == 0) stile = atomicAdd(&g_tscan, 1);
        __syncthreads();
        int t = stile;
        if (t >= SCAN_BLOCKS) break;

        int i = t * 256 + tid;
        int v = (i < N_NODES) ? g_deg[i] : 0;
        sv[tid] = v;
        __syncthreads();
#pragma unroll
        for (int d = 1; d < 256; d <<= 1) {
            int u = (tid >= d) ? sv[tid - d] : 0;
            __syncthreads();
            sv[tid] += u;
            __syncthreads();
        }
        int incl = sv[tid];
        int bsum = sv[255];

        if (tid == 0) {
            if (t == 0) {
                atomicExch(&g_state[0], (2ull << 32) | (unsigned)bsum);
                sexcl = 0;
            } else {
                atomicExch(&g_state[t], (1ull << 32) | (unsigned)bsum);
                int excl = 0;
                int j = t - 1;
                while (true) {
                    unsigned long long s;
                    do { s = atomicAdd(&g_state[j], 0ull); } while ((s >> 32) == 0);
                    excl += (int)(unsigned)s;
                    if ((s >> 32) == 2ull) break;
                    j--;
                }
                atomicExch(&g_state[t], (2ull << 32) | (unsigned)(excl + bsum));
                sexcl = excl;
            }
        }
        __syncthreads();
        int ex = sexcl + incl - v;
        if (i < N_NODES) { g_off[i] = ex; g_cur[i] = ex; }
        if (t == SCAN_BLOCKS - 1 && tid == 255) g_off[N_NODES] = sexcl + bsum;
        __syncthreads();
    }
    grid_barrier(&g_barC);

    // ---- P3: scatter ----
    if (is64) {
        const long long* p = (const long long*)ei;
        for (int e = gthread; e < N_EDGES; e += gsize) {
            int r = (int)p[e];
            int c = (int)p[e + N_EDGES];
            if ((unsigned)r < N_NODES && (unsigned)c < N_NODES) {
                int pos = atomicAdd(&g_cur[r], 1);
                g_scol[pos] = c;
            }
        }
    } else {
        const int* p = (const int*)ei;
        for (int e = gthread; e < N_EDGES; e += gsize) {
            int r = p[e];
            int c = p[e + N_EDGES];
            if ((unsigned)r < N_NODES && (unsigned)c < N_NODES) {
                int pos = atomicAdd(&g_cur[r], 1);
                g_scol[pos] = c;
            }
        }
    }
}

// ---------------------------------------------------------------------------
// K_XW: x fp32->fp16 (+pad) and W fp32->fp16, fused.
__global__ void k_xw(const float* __restrict__ x, const float* __restrict__ W) {
    if (blockIdx.x < 16) {
        int i = blockIdx.x * 256 + threadIdx.x;
        float4 v = ((const float4*)W)[i];
        __half2 h0 = __floats2half2_rn(v.x, v.y);
        __half2 h1 = __floats2half2_rn(v.z, v.w);
        uint2 st = { *(unsigned*)&h0, *(unsigned*)&h1 };
        ((uint2*)g_Wh)[i] = st;
    } else {
        int i = (blockIdx.x - 16) * 256 + threadIdx.x;
        const int TOT4 = N_PAD * CIN / 4;
        if (i >= TOT4) return;
        const int REAL4 = N_NODES * CIN / 4;
        float4 v = (i < REAL4) ? ((const float4*)x)[i] : make_float4(0.f, 0.f, 0.f, 0.f);
        __half2 h0 = __floats2half2_rn(v.x, v.y);
        __half2 h1 = __floats2half2_rn(v.z, v.w);
        uint2 st = { *(unsigned*)&h0, *(unsigned*)&h1 };
        ((uint2*)g_xh)[i] = st;
    }
}

// ---------------------------------------------------------------------------
// K_LINEAR: x_t = x @ W^T + b via HMMA, 64 nodes x 128 oc per block.
#define LSTRIDE 136
#define A_HALVES (64 * LSTRIDE)
__global__ void __launch_bounds__(256) k_linear(const float* __restrict__ b) {
    extern __shared__ __align__(16) __half sm[];
    __half* As = sm;
    __half* Bs = sm + A_HALVES;

    int tid = threadIdx.x, lane = tid & 31, warp = tid >> 5;
    int wm = warp & 3;
    int wn = warp >> 2;
    int m0 = blockIdx.x * 64;

    unsigned a_base = (unsigned)__cvta_generic_to_shared(As);
    unsigned b_base = (unsigned)__cvta_generic_to_shared(Bs);

    for (int c = tid; c < 64 * 16; c += 256) {
        int row = c >> 4, col = c & 15;
        cp16(a_base + row * (LSTRIDE * 2) + col * 16,
             &g_xh[(size_t)(m0 + row) * CIN + col * 8]);
    }
    for (int c = tid; c < 128 * 16; c += 256) {
        int row = c >> 4, col = c & 15;
        cp16(b_base + row * (LSTRIDE * 2) + col * 16,
             &g_Wh[row * CIN + col * 8]);
    }
    asm volatile("cp.async.commit_group;");
    asm volatile("cp.async.wait_group 0;" ::: "memory");
    __syncthreads();

    float acc[8][4];
#pragma unroll
    for (int i = 0; i < 8; i++)
#pragma unroll
        for (int j = 0; j < 4; j++) acc[i][j] = 0.f;

    int m_warp = wm * 16;
    unsigned a_off = a_base + ((m_warp + (lane & 15)) * LSTRIDE + (lane >> 4) * 8) * 2;
    unsigned b_off = b_base + (wn * 64 + ((lane >> 4) << 3) + (lane & 7)) * (LSTRIDE * 2)
                            + (((lane >> 3) & 1) * 8) * 2;

#pragma unroll
    for (int kk = 0; kk < 8; kk++) {
        unsigned a[4];
        ldsm_x4(a, a_off + kk * 32);
#pragma unroll
        for (int ntp = 0; ntp < 4; ntp++) {
            unsigned bf[4];
            ldsm_x4(bf, b_off + (ntp * 16 * LSTRIDE) * 2 + kk * 32);
            mma16816(acc[ntp * 2],     a, bf);
            mma16816(acc[ntp * 2 + 1], a, bf + 2);
        }
    }

    int row0 = m_warp + (lane >> 2);
#pragma unroll
    for (int nt = 0; nt < 8; nt++) {
        int col = wn * 64 + nt * 8 + (lane & 3) * 2;
        float2 bv = *(const float2*)&b[col];
        int na = m0 + row0;
        if (na < N_NODES) {
            __half2 h = __floats2half2_rn(acc[nt][0] + bv.x, acc[nt][1] + bv.y);
            *(__half2*)&g_xt[(size_t)na * COUT + col] = h;
        }
        int nb = na + 8;
        if (nb < N_NODES) {
            __half2 h = __floats2half2_rn(acc[nt][2] + bv.x, acc[nt][3] + bv.y);
            *(__half2*)&g_xt[(size_t)nb * COUT + col] = h;
        }
    }
}

// ---------------------------------------------------------------------------
// K_GATHER: warp-per-node segmented sum over CSR (fp16, fp32 accum) + tanh.
__global__ void k_gather(float* __restrict__ out) {
    int gw   = (blockIdx.x * blockDim.x + threadIdx.x) >> 5;
    int lane = threadIdx.x & 31;
    if (gw >= N_NODES) return;

    int s = g_off[gw];
    int e = g_off[gw + 1];
    const uint2* xt2 = (const uint2*)g_xt;

    float4 accA = make_float4(0.f, 0.f, 0.f, 0.f);
    float4 accB = make_float4(0.f, 0.f, 0.f, 0.f);

    int i = s;
    for (; i + 3 < e; i += 4) {
        int c0 = __ldg(&g_scol[i]);
        int c1 = __ldg(&g_scol[i + 1]);
        int c2 = __ldg(&g_scol[i + 2]);
        int c3 = __ldg(&g_scol[i + 3]);
        uint2 r0 = __ldg(&xt2[(size_t)c0 * 32 + lane]);
        uint2 r1 = __ldg(&xt2[(size_t)c1 * 32 + lane]);
        uint2 r2 = __ldg(&xt2[(size_t)c2 * 32 + lane]);
        uint2 r3 = __ldg(&xt2[(size_t)c3 * 32 + lane]);
        float2 a0 = __half22float2(*(const __half2*)&r0.x);
        float2 a1 = __half22float2(*(const __half2*)&r0.y);
        float2 b0 = __half22float2(*(const __half2*)&r1.x);
        float2 b1 = __half22float2(*(const __half2*)&r1.y);
        accA.x += a0.x; accA.y += a0.y; accA.z += a1.x; accA.w += a1.y;
        accB.x += b0.x; accB.y += b0.y; accB.z += b1.x; accB.w += b1.y;
        float2 d0 = __half22float2(*(const __half2*)&r2.x);
        float2 d1 = __half22float2(*(const __half2*)&r2.y);
        float2 e0 = __half22float2(*(const __half2*)&r3.x);
        float2 e1 = __half22float2(*(const __half2*)&r3.y);
        accA.x += d0.x; accA.y += d0.y; accA.z += d1.x; accA.w += d1.y;
        accB.x += e0.x; accB.y += e0.y; accB.z += e1.x; accB.w += e1.y;
    }
    for (; i < e; i++) {
        int c = __ldg(&g_scol[i]);
        uint2 r = __ldg(&xt2[(size_t)c * 32 + lane]);
        float2 p0 = __half22float2(*(const __half2*)&r.x);
        float2 p1 = __half22float2(*(const __half2*)&r.y);
        accA.x += p0.x; accA.y += p0.y; accA.z += p1.x; accA.w += p1.y;
    }

    float4 r = make_float4(tanhf(accA.x + accB.x), tanhf(accA.y + accB.y),
                           tanhf(accA.z + accB.z), tanhf(accA.w + accB.w));
    ((float4*)out)[(size_t)gw * 32 + lane] = r;
}

// ---------------------------------------------------------------------------
extern "C" void kernel_launch(void* const* d_in, const int* in_sizes, int n_in,
                              void* d_out, int out_size) {
    const float* x  = (const float*)d_in[0];
    const void*  ei = d_in[1];
    const float* W  = (const float*)d_in[2];
    const float* b  = (const float*)d_in[3];
    float*       out = (float*)d_out;

    static cudaStream_t s1 = nullptr;
    static cudaEvent_t  evFork = nullptr, evJoin = nullptr;
    if (!s1) {
        cudaStreamCreateWithFlags(&s1, cudaStreamNonBlocking);
        cudaEventCreateWithFlags(&evFork, cudaEventDisableTiming);
        cudaEventCreateWithFlags(&evJoin, cudaEventDisableTiming);
        cudaFuncSetAttribute(k_linear, cudaFuncAttributeMaxDynamicSharedMemorySize,
                             (A_HALVES + 128 * LSTRIDE) * 2);
    }
    const int SMEM_LIN = (A_HALVES + 128 * LSTRIDE) * 2;   // 52.2 KB

    cudaEventRecord(evFork, 0);
    cudaStreamWaitEvent(s1, evFork, 0);

    // Side stream: entire CSR build as ONE persistent kernel.
    k_csr<<<NBLK, 256, 0, s1>>>(ei);                         // launch 1

    // Main stream: convert + linear (overlap CSR).
    k_xw<<<16 + (N_PAD * CIN / 4 + 255) / 256, 256>>>(x, W); // launch 2
    k_linear<<<(N_NODES + 63) / 64, 256, SMEM_LIN>>>(b);     // launch 3

    cudaEventRecord(evJoin, s1);
    cudaStreamWaitEvent(0, evJoin, 0);
    k_gather<<<(N_NODES * 32 + 255) / 256, 256>>>(out);      // launch 4 (profiled)
}

// round 12
// speedup vs baseline: 1.0399x; 1.0399x over previous
#include <cuda_runtime.h>
#include <cuda_fp16.h>

#define N_NODES 50000
#define N_PAD   50048
#define N_EDGES 800000
#define CIN 128
#define COUT 128

#define SCAN_BLOCKS ((N_NODES + 255) / 256)   // 196

// Scratch (allocation-free: __device__ globals)
__device__ int      g_is64;
__device__ int      g_deg[N_NODES];
__device__ int      g_off[N_NODES + 1];
__device__ int      g_cur[N_NODES];
__device__ int      g_ticket;
__device__ unsigned long long g_state[SCAN_BLOCKS];
__device__ int      g_scol[N_EDGES];
__device__ __half   g_xh[(size_t)N_PAD * CIN];
__device__ __half   g_Wh[COUT * CIN];
__device__ __half   g_xt[(size_t)N_NODES * COUT];

// ---------------------------------------------------------------------------
__device__ __forceinline__ void ldsm_x4(unsigned* r, unsigned addr) {
    asm volatile("ldmatrix.sync.aligned.m8n8.x4.shared.b16 {%0,%1,%2,%3}, [%4];"
                 : "=r"(r[0]), "=r"(r[1]), "=r"(r[2]), "=r"(r[3]) : "r"(addr));
}
__device__ __forceinline__ void mma16816(float* c, const unsigned* a, const unsigned* b) {
    asm volatile(
        "mma.sync.aligned.m16n8k16.row.col.f32.f16.f16.f32 "
        "{%0,%1,%2,%3}, {%4,%5,%6,%7}, {%8,%9}, {%0,%1,%2,%3};"
        : "+f"(c[0]), "+f"(c[1]), "+f"(c[2]), "+f"(c[3])
        : "r"(a[0]), "r"(a[1]), "r"(a[2]), "r"(a[3]), "r"(b[0]), "r"(b[1]));
}
__device__ __forceinline__ void cp16(unsigned dst, const void* src) {
    asm volatile("cp.async.cg.shared.global [%0], [%1], 16;" :: "r"(dst), "l"(src));
}

// ---------------------------------------------------------------------------
// K_INIT: zero g_deg + scan state + ticket + dtype detect.
__global__ void k_init(const void* ei_raw) {
    int i = blockIdx.x * blockDim.x + threadIdx.x;
    if (i < N_NODES) g_deg[i] = 0;
    if (i < SCAN_BLOCKS) g_state[i] = 0ull;
    if (i == 0) g_ticket = 0;
    if (blockIdx.x == 0 && threadIdx.x < 32) {
        const long long* p = (const long long*)ei_raw;
        int lane = threadIdx.x;
        long long v0 = p[lane];
        long long v1 = p[lane + 32];
        int bad = (v0 < 0 || v0 >= N_NODES || v1 < 0 || v1 >= N_NODES);
        unsigned m = __ballot_sync(0xffffffffu, bad);
        if (lane == 0) g_is64 = (m == 0);
    }
}

// ---------------------------------------------------------------------------
// K_COUNT: 4 edges/thread, vectorized row loads, return-free atomics (RED).
__global__ void k_count(const void* __restrict__ ei) {
    int e0 = (blockIdx.x * blockDim.x + threadIdx.x) * 4;
    if (e0 >= N_EDGES) return;
    if (g_is64) {
        const longlong2* p2 = (const longlong2*)ei;
        longlong2 ra = p2[e0 / 2];
        longlong2 rb = p2[e0 / 2 + 1];
        int r0 = (int)ra.x, r1 = (int)ra.y, r2 = (int)rb.x, r3 = (int)rb.y;
        if ((unsigned)r0 < N_NODES) atomicAdd(&g_deg[r0], 1);
        if ((unsigned)r1 < N_NODES) atomicAdd(&g_deg[r1], 1);
        if ((unsigned)r2 < N_NODES) atomicAdd(&g_deg[r2], 1);
        if ((unsigned)r3 < N_NODES) atomicAdd(&g_deg[r3], 1);
    } else {
        int4 r = *(const int4*)((const int*)ei + e0);
        if ((unsigned)r.x < N_NODES) atomicAdd(&g_deg[r.x], 1);
        if ((unsigned)r.y < N_NODES) atomicAdd(&g_deg[r.y], 1);
        if ((unsigned)r.z < N_NODES) atomicAdd(&g_deg[r.z], 1);
        if ((unsigned)r.w < N_NODES) atomicAdd(&g_deg[r.w], 1);
    }
}

// ---------------------------------------------------------------------------
// K_SCAN: single-pass decoupled-lookback exclusive scan.
__global__ void k_scanDL() {
    __shared__ int sv[256];
    __shared__ int sbid, sexcl;
    int tid = threadIdx.x;
    if (tid == 0) sbid = atomicAdd(&g_ticket, 1);
    __syncthreads();
    int bid = sbid;
    int i = bid * 256 + tid;
    int v = (i < N_NODES) ? g_deg[i] : 0;
    sv[tid] = v;
    __syncthreads();
#pragma unroll
    for (int d = 1; d < 256; d <<= 1) {
        int u = (tid >= d) ? sv[tid - d] : 0;
        __syncthreads();
        sv[tid] += u;
        __syncthreads();
    }
    int incl = sv[tid];
    int bsum = sv[255];

    if (tid == 0) {
        if (bid == 0) {
            atomicExch(&g_state[0], (2ull << 32) | (unsigned)bsum);
            sexcl = 0;
        } else {
            atomicExch(&g_state[bid], (1ull << 32) | (unsigned)bsum);
            int excl = 0;
            int j = bid - 1;
            while (true) {
                unsigned long long s;
                do { s = atomicAdd(&g_state[j], 0ull); } while ((s >> 32) == 0);
                excl += (int)(unsigned)s;
                if ((s >> 32) == 2ull) break;
                j--;
            }
            atomicExch(&g_state[bid], (2ull << 32) | (unsigned)(excl + bsum));
            sexcl = excl;
        }
    }
    __syncthreads();
    int e = sexcl + incl - v;
    if (i < N_NODES) { g_off[i] = e; g_cur[i] = e; }
    if (bid == SCAN_BLOCKS - 1 && tid == 255) g_off[N_NODES] = sexcl + bsum;
}

// ---------------------------------------------------------------------------
// K_SCATTER: 4 edges/thread — 4 independent atomic->store chains (MLP=4).
__global__ void k_scatter(const void* __restrict__ ei) {
    int e0 = (blockIdx.x * blockDim.x + threadIdx.x) * 4;
    if (e0 >= N_EDGES) return;
    int r[4], c[4];
    if (g_is64) {
        const longlong2* p2 = (const longlong2*)ei;
        longlong2 ra = p2[e0 / 2];
        longlong2 rb = p2[e0 / 2 + 1];
        longlong2 ca = p2[(N_EDGES + e0) / 2];
        longlong2 cb = p2[(N_EDGES + e0) / 2 + 1];
        r[0] = (int)ra.x; r[1] = (int)ra.y; r[2] = (int)rb.x; r[3] = (int)rb.y;
        c[0] = (int)ca.x; c[1] = (int)ca.y; c[2] = (int)cb.x; c[3] = (int)cb.y;
    } else {
        int4 rv = *(const int4*)((const int*)ei + e0);
        int4 cv = *(const int4*)((const int*)ei + N_EDGES + e0);
        r[0] = rv.x; r[1] = rv.y; r[2] = rv.z; r[3] = rv.w;
        c[0] = cv.x; c[1] = cv.y; c[2] = cv.z; c[3] = cv.w;
    }
    int pos[4];
#pragma unroll
    for (int j = 0; j < 4; j++) {
        bool ok = (unsigned)r[j] < N_NODES && (unsigned)c[j] < N_NODES;
        pos[j] = ok ? atomicAdd(&g_cur[r[j]], 1) : -1;
    }
#pragma unroll
    for (int j = 0; j < 4; j++)
        if (pos[j] >= 0) g_scol[pos[j]] = c[j];
}

// ---------------------------------------------------------------------------
// K_XW: x fp32->fp16 (+pad) and W fp32->fp16, fused.
__global__ void k_xw(const float* __restrict__ x, const float* __restrict__ W) {
    if (blockIdx.x < 16) {
        int i = blockIdx.x * 256 + threadIdx.x;
        float4 v = ((const float4*)W)[i];
        __half2 h0 = __floats2half2_rn(v.x, v.y);
        __half2 h1 = __floats2half2_rn(v.z, v.w);
        uint2 st = { *(unsigned*)&h0, *(unsigned*)&h1 };
        ((uint2*)g_Wh)[i] = st;
    } else {
        int i = (blockIdx.x - 16) * 256 + threadIdx.x;
        const int TOT4 = N_PAD * CIN / 4;
        if (i >= TOT4) return;
        const int REAL4 = N_NODES * CIN / 4;
        float4 v = (i < REAL4) ? ((const float4*)x)[i] : make_float4(0.f, 0.f, 0.f, 0.f);
        __half2 h0 = __floats2half2_rn(v.x, v.y);
        __half2 h1 = __floats2half2_rn(v.z, v.w);
        uint2 st = { *(unsigned*)&h0, *(unsigned*)&h1 };
        ((uint2*)g_xh)[i] = st;
    }
}

// ---------------------------------------------------------------------------
// K_LINEAR: x_t = x @ W^T + b via HMMA, 64 nodes x 128 oc per block.
#define LSTRIDE 136
#define A_HALVES (64 * LSTRIDE)
__global__ void __launch_bounds__(256) k_linear(const float* __restrict__ b) {
    extern __shared__ __align__(16) __half sm[];
    __half* As = sm;
    __half* Bs = sm + A_HALVES;

    int tid = threadIdx.x, lane = tid & 31, warp = tid >> 5;
    int wm = warp & 3;
    int wn = warp >> 2;
    int m0 = blockIdx.x * 64;

    unsigned a_base = (unsigned)__cvta_generic_to_shared(As);
    unsigned b_base = (unsigned)__cvta_generic_to_shared(Bs);

    for (int c = tid; c < 64 * 16; c += 256) {
        int row = c >> 4, col = c & 15;
        cp16(a_base + row * (LSTRIDE * 2) + col * 16,
             &g_xh[(size_t)(m0 + row) * CIN + col * 8]);
    }
    for (int c = tid; c < 128 * 16; c += 256) {
        int row = c >> 4, col = c & 15;
        cp16(b_base + row * (LSTRIDE * 2) + col * 16,
             &g_Wh[row * CIN + col * 8]);
    }
    asm volatile("cp.async.commit_group;");
    asm volatile("cp.async.wait_group 0;" ::: "memory");
    __syncthreads();

    float acc[8][4];
#pragma unroll
    for (int i = 0; i < 8; i++)
#pragma unroll
        for (int j = 0; j < 4; j++) acc[i][j] = 0.f;

    int m_warp = wm * 16;
    unsigned a_off = a_base + ((m_warp + (lane & 15)) * LSTRIDE + (lane >> 4) * 8) * 2;
    unsigned b_off = b_base + (wn * 64 + ((lane >> 4) << 3) + (lane & 7)) * (LSTRIDE * 2)
                            + (((lane >> 3) & 1) * 8) * 2;

#pragma unroll
    for (int kk = 0; kk < 8; kk++) {
        unsigned a[4];
        ldsm_x4(a, a_off + kk * 32);
#pragma unroll
        for (int ntp = 0; ntp < 4; ntp++) {
            unsigned bf[4];
            ldsm_x4(bf, b_off + (ntp * 16 * LSTRIDE) * 2 + kk * 32);
            mma16816(acc[ntp * 2],     a, bf);
            mma16816(acc[ntp * 2 + 1], a, bf + 2);
        }
    }

    int row0 = m_warp + (lane >> 2);
#pragma unroll
    for (int nt = 0; nt < 8; nt++) {
        int col = wn * 64 + nt * 8 + (lane & 3) * 2;
        float2 bv = *(const float2*)&b[col];
        int na = m0 + row0;
        if (na < N_NODES) {
            __half2 h = __floats2half2_rn(acc[nt][0] + bv.x, acc[nt][1] + bv.y);
            *(__half2*)&g_xt[(size_t)na * COUT + col] = h;
        }
        int nb = na + 8;
        if (nb < N_NODES) {
            __half2 h = __floats2half2_rn(acc[nt][2] + bv.x, acc[nt][3] + bv.y);
            *(__half2*)&g_xt[(size_t)nb * COUT + col] = h;
        }
    }
}

// ---------------------------------------------------------------------------
// K_GATHER: warp-per-node segmented sum. Edge PAIRS pre-added in fp16
// (1 HADD2 per half2-pair) then converted + accumulated fp32 -> ~45% fewer
// math issues on an issue-bound kernel. fp32 accum across pairs + tanh.
__global__ void k_gather(float* __restrict__ out) {
    int gw   = (blockIdx.x * blockDim.x + threadIdx.x) >> 5;
    int lane = threadIdx.x & 31;
    if (gw >= N_NODES) return;

    int s = g_off[gw];
    int e = g_off[gw + 1];
    const uint2* xt2 = (const uint2*)g_xt;

    float4 accA = make_float4(0.f, 0.f, 0.f, 0.f);
    float4 accB = make_float4(0.f, 0.f, 0.f, 0.f);

    int i = s;
    for (; i + 3 < e; i += 4) {
        int c0 = __ldg(&g_scol[i]);
        int c1 = __ldg(&g_scol[i + 1]);
        int c2 = __ldg(&g_scol[i + 2]);
        int c3 = __ldg(&g_scol[i + 3]);
        uint2 r0 = __ldg(&xt2[(size_t)c0 * 32 + lane]);
        uint2 r1 = __ldg(&xt2[(size_t)c1 * 32 + lane]);
        uint2 r2 = __ldg(&xt2[(size_t)c2 * 32 + lane]);
        uint2 r3 = __ldg(&xt2[(size_t)c3 * 32 + lane]);
        // fp16 pair pre-add (one rounding per pair, per channel)
        __half2 pa0 = __hadd2(*(const __half2*)&r0.x, *(const __half2*)&r1.x);
        __half2 pa1 = __hadd2(*(const __half2*)&r0.y, *(const __half2*)&r1.y);
        __half2 pb0 = __hadd2(*(const __half2*)&r2.x, *(const __half2*)&r3.x);
        __half2 pb1 = __hadd2(*(const __half2*)&r2.y, *(const __half2*)&r3.y);
        float2 fa0 = __half22float2(pa0);
        float2 fa1 = __half22float2(pa1);
        float2 fb0 = __half22float2(pb0);
        float2 fb1 = __half22float2(pb1);
        accA.x += fa0.x; accA.y += fa0.y; accA.z += fa1.x; accA.w += fa1.y;
        accB.x += fb0.x; accB.y += fb0.y; accB.z += fb1.x; accB.w += fb1.y;
    }
    for (; i < e; i++) {
        int c = __ldg(&g_scol[i]);
        uint2 r = __ldg(&xt2[(size_t)c * 32 + lane]);
        float2 p0 = __half22float2(*(const __half2*)&r.x);
        float2 p1 = __half22float2(*(const __half2*)&r.y);
        accA.x += p0.x; accA.y += p0.y; accA.z += p1.x; accA.w += p1.y;
    }

    float4 r = make_float4(tanhf(accA.x + accB.x), tanhf(accA.y + accB.y),
                           tanhf(accA.z + accB.z), tanhf(accA.w + accB.w));
    ((float4*)out)[(size_t)gw * 32 + lane] = r;
}

// ---------------------------------------------------------------------------
extern "C" void kernel_launch(void* const* d_in, const int* in_sizes, int n_in,
                              void* d_out, int out_size) {
    const float* x  = (const float*)d_in[0];
    const void*  ei = d_in[1];
    const float* W  = (const float*)d_in[2];
    const float* b  = (const float*)d_in[3];
    float*       out = (float*)d_out;

    static cudaStream_t s1 = nullptr;
    static cudaEvent_t  evFork = nullptr, evJoin = nullptr;
    if (!s1) {
        cudaStreamCreateWithFlags(&s1, cudaStreamNonBlocking);
        cudaEventCreateWithFlags(&evFork, cudaEventDisableTiming);
        cudaEventCreateWithFlags(&evJoin, cudaEventDisableTiming);
        cudaFuncSetAttribute(k_linear, cudaFuncAttributeMaxDynamicSharedMemorySize,
                             (A_HALVES + 128 * LSTRIDE) * 2);
    }
    const int SMEM_LIN = (A_HALVES + 128 * LSTRIDE) * 2;   // 52.2 KB

    k_init<<<SCAN_BLOCKS, 256>>>(ei);                       // launch 1
    cudaEventRecord(evFork, 0);
    cudaStreamWaitEvent(s1, evFork, 0);

    // Side stream: CSR chain.
    k_count<<<(N_EDGES / 4 + 255) / 256, 256, 0, s1>>>(ei); // 2
    k_scanDL<<<SCAN_BLOCKS, 256, 0, s1>>>();                // 3
    k_scatter<<<(N_EDGES / 4 + 255) / 256, 256, 0, s1>>>(ei); // 4 (profiled)

    // Main stream: convert + linear (overlap CSR chain).
    k_xw<<<16 + (N_PAD * CIN / 4 + 255) / 256, 256>>>(x, W); // 5
    k_linear<<<(N_NODES + 63) / 64, 256, SMEM_LIN>>>(b);     // 6

    cudaEventRecord(evJoin, s1);
    cudaStreamWaitEvent(0, evJoin, 0);
    k_gather<<<(N_NODES * 32 + 255) / 256, 256>>>(out);      // 7
}

// round 13
// speedup vs baseline: 1.1829x; 1.1375x over previous
#include <cuda_runtime.h>
#include <cuda_fp16.h>

#define N_NODES 50000
#define N_PAD   50048
#define N_EDGES 800000
#define CIN 128
#define COUT 128

#define SCAN_BLOCKS ((N_NODES + 255) / 256)   // 196
#define SCOL_CAP (N_EDGES + 4 * N_NODES)      // padded CSR capacity

// Scratch (allocation-free: __device__ globals)
__device__ int      g_is64;
__device__ int      g_deg[N_NODES];
__device__ int      g_off[N_NODES + 1];
__device__ int      g_ticket;
__device__ unsigned long long g_state[SCAN_BLOCKS];
__device__ int      g_rank[N_EDGES];
__device__ int      g_scol[SCOL_CAP];
__device__ __half   g_xh[(size_t)N_PAD * CIN];
__device__ __half   g_Wh[COUT * CIN];
__device__ __half   g_xt[(size_t)(N_NODES + 1) * COUT];   // +1 zero row for padding

// ---------------------------------------------------------------------------
__device__ __forceinline__ void ldsm_x4(unsigned* r, unsigned addr) {
    asm volatile("ldmatrix.sync.aligned.m8n8.x4.shared.b16 {%0,%1,%2,%3}, [%4];"
                 : "=r"(r[0]), "=r"(r[1]), "=r"(r[2]), "=r"(r[3]) : "r"(addr));
}
__device__ __forceinline__ void mma16816(float* c, const unsigned* a, const unsigned* b) {
    asm volatile(
        "mma.sync.aligned.m16n8k16.row.col.f32.f16.f16.f32 "
        "{%0,%1,%2,%3}, {%4,%5,%6,%7}, {%8,%9}, {%0,%1,%2,%3};"
        : "+f"(c[0]), "+f"(c[1]), "+f"(c[2]), "+f"(c[3])
        : "r"(a[0]), "r"(a[1]), "r"(a[2]), "r"(a[3]), "r"(b[0]), "r"(b[1]));
}
__device__ __forceinline__ void cp16(unsigned dst, const void* src) {
    asm volatile("cp.async.cg.shared.global [%0], [%1], 16;" :: "r"(dst), "l"(src));
}

// ---------------------------------------------------------------------------
// K_INIT: zero g_deg + scan state + ticket + dtype detect.
__global__ void k_init(const void* ei_raw) {
    int i = blockIdx.x * blockDim.x + threadIdx.x;
    if (i < N_NODES) g_deg[i] = 0;
    if (i < SCAN_BLOCKS) g_state[i] = 0ull;
    if (i == 0) g_ticket = 0;
    if (blockIdx.x == 0 && threadIdx.x < 32) {
        const long long* p = (const long long*)ei_raw;
        int lane = threadIdx.x;
        long long v0 = p[lane];
        long long v1 = p[lane + 32];
        int bad = (v0 < 0 || v0 >= N_NODES || v1 < 0 || v1 >= N_NODES);
        unsigned m = __ballot_sync(0xffffffffu, bad);
        if (lane == 0) g_is64 = (m == 0);
    }
}

// ---------------------------------------------------------------------------
// K_COUNT: degree count; atomic RETURN = edge's rank within its row.
__global__ void k_count(const void* __restrict__ ei) {
    int e = blockIdx.x * blockDim.x + threadIdx.x;
    if (e >= N_EDGES) return;
    int r = g_is64 ? (int)((const long long*)ei)[e] : ((const int*)ei)[e];
    int rank = ((unsigned)r < N_NODES) ? atomicAdd(&g_deg[r], 1) : -1;
    g_rank[e] = rank;
}

// ---------------------------------------------------------------------------
// K_SCAN: decoupled-lookback exclusive scan of PADDED degrees
// (ceil(deg/4)*4 -> every CSR segment 4-aligned). Also pre-fills g_scol
// with the zero-row index so padding slots contribute 0 to the gather.
__global__ void k_scanDL() {
    // streaming pre-fill (independent of scan; ordered by kernel boundary)
    for (int i = blockIdx.x * 256 + threadIdx.x; i < SCOL_CAP; i += SCAN_BLOCKS * 256)
        g_scol[i] = N_NODES;

    __shared__ int sv[256];
    __shared__ int sbid, sexcl;
    int tid = threadIdx.x;
    if (tid == 0) sbid = atomicAdd(&g_ticket, 1);
    __syncthreads();
    int bid = sbid;
    int i = bid * 256 + tid;
    int v = (i < N_NODES) ? ((g_deg[i] + 3) & ~3) : 0;   // padded degree
    sv[tid] = v;
    __syncthreads();
#pragma unroll
    for (int d = 1; d < 256; d <<= 1) {
        int u = (tid >= d) ? sv[tid - d] : 0;
        __syncthreads();
        sv[tid] += u;
        __syncthreads();
    }
    int incl = sv[tid];
    int bsum = sv[255];

    if (tid == 0) {
        if (bid == 0) {
            atomicExch(&g_state[0], (2ull << 32) | (unsigned)bsum);
            sexcl = 0;
        } else {
            atomicExch(&g_state[bid], (1ull << 32) | (unsigned)bsum);
            int excl = 0;
            int j = bid - 1;
            while (true) {
                unsigned long long s;
                do { s = atomicAdd(&g_state[j], 0ull); } while ((s >> 32) == 0);
                excl += (int)(unsigned)s;
                if ((s >> 32) == 2ull) break;
                j--;
            }
            atomicExch(&g_state[bid], (2ull << 32) | (unsigned)(excl + bsum));
            sexcl = excl;
        }
    }
    __syncthreads();
    if (i < N_NODES) g_off[i] = sexcl + incl - v;
    if (bid == SCAN_BLOCKS - 1 && tid == 255) g_off[N_NODES] = sexcl + bsum;
}

// ---------------------------------------------------------------------------
// K_SCATTER: atomic-free — placement = row base + precomputed rank.
__global__ void k_scatter(const void* __restrict__ ei) {
    int e = blockIdx.x * blockDim.x + threadIdx.x;
    if (e >= N_EDGES) return;
    int r, c;
    if (g_is64) {
        const long long* p = (const long long*)ei;
        r = (int)p[e];
        c = (int)p[e + N_EDGES];
    } else {
        const int* p = (const int*)ei;
        r = p[e];
        c = p[e + N_EDGES];
    }
    int rank = g_rank[e];
    if (rank >= 0 && (unsigned)c < N_NODES)
        g_scol[g_off[r] + rank] = c;
}

// ---------------------------------------------------------------------------
// K_XW: x fp32->fp16 (+pad), W fp32->fp16, and zero row N_NODES of g_xt.
__global__ void k_xw(const float* __restrict__ x, const float* __restrict__ W) {
    if (blockIdx.x < 16) {
        int i = blockIdx.x * 256 + threadIdx.x;
        float4 v = ((const float4*)W)[i];
        __half2 h0 = __floats2half2_rn(v.x, v.y);
        __half2 h1 = __floats2half2_rn(v.z, v.w);
        uint2 st = { *(unsigned*)&h0, *(unsigned*)&h1 };
        ((uint2*)g_Wh)[i] = st;
        if (blockIdx.x == 0 && threadIdx.x < 32) {   // zero row for CSR padding
            uint2 z = {0u, 0u};
            ((uint2*)&g_xt[(size_t)N_NODES * COUT])[threadIdx.x] = z;
        }
    } else {
        int i = (blockIdx.x - 16) * 256 + threadIdx.x;
        const int TOT4 = N_PAD * CIN / 4;
        if (i >= TOT4) return;
        const int REAL4 = N_NODES * CIN / 4;
        float4 v = (i < REAL4) ? ((const float4*)x)[i] : make_float4(0.f, 0.f, 0.f, 0.f);
        __half2 h0 = __floats2half2_rn(v.x, v.y);
        __half2 h1 = __floats2half2_rn(v.z, v.w);
        uint2 st = { *(unsigned*)&h0, *(unsigned*)&h1 };
        ((uint2*)g_xh)[i] = st;
    }
}

// ---------------------------------------------------------------------------
// K_LINEAR: x_t = x @ W^T + b via HMMA, 64 nodes x 128 oc per block.
#define LSTRIDE 136
#define A_HALVES (64 * LSTRIDE)
__global__ void __launch_bounds__(256) k_linear(const float* __restrict__ b) {
    extern __shared__ __align__(16) __half sm[];
    __half* As = sm;
    __half* Bs = sm + A_HALVES;

    int tid = threadIdx.x, lane = tid & 31, warp = tid >> 5;
    int wm = warp & 3;
    int wn = warp >> 2;
    int m0 = blockIdx.x * 64;

    unsigned a_base = (unsigned)__cvta_generic_to_shared(As);
    unsigned b_base = (unsigned)__cvta_generic_to_shared(Bs);

    for (int c = tid; c < 64 * 16; c += 256) {
        int row = c >> 4, col = c & 15;
        cp16(a_base + row * (LSTRIDE * 2) + col * 16,
             &g_xh[(size_t)(m0 + row) * CIN + col * 8]);
    }
    for (int c = tid; c < 128 * 16; c += 256) {
        int row = c >> 4, col = c & 15;
        cp16(b_base + row * (LSTRIDE * 2) + col * 16,
             &g_Wh[row * CIN + col * 8]);
    }
    asm volatile("cp.async.commit_group;");
    asm volatile("cp.async.wait_group 0;" ::: "memory");
    __syncthreads();

    float acc[8][4];
#pragma unroll
    for (int i = 0; i < 8; i++)
#pragma unroll
        for (int j = 0; j < 4; j++) acc[i][j] = 0.f;

    int m_warp = wm * 16;
    unsigned a_off = a_base + ((m_warp + (lane & 15)) * LSTRIDE + (lane >> 4) * 8) * 2;
    unsigned b_off = b_base + (wn * 64 + ((lane >> 4) << 3) + (lane & 7)) * (LSTRIDE * 2)
                            + (((lane >> 3) & 1) * 8) * 2;

#pragma unroll
    for (int kk = 0; kk < 8; kk++) {
        unsigned a[4];
        ldsm_x4(a, a_off + kk * 32);
#pragma unroll
        for (int ntp = 0; ntp < 4; ntp++) {
            unsigned bf[4];
            ldsm_x4(bf, b_off + (ntp * 16 * LSTRIDE) * 2 + kk * 32);
            mma16816(acc[ntp * 2],     a, bf);
            mma16816(acc[ntp * 2 + 1], a, bf + 2);
        }
    }

    int row0 = m_warp + (lane >> 2);
#pragma unroll
    for (int nt = 0; nt < 8; nt++) {
        int col = wn * 64 + nt * 8 + (lane & 3) * 2;
        float2 bv = *(const float2*)&b[col];
        int na = m0 + row0;
        if (na < N_NODES) {
            __half2 h = __floats2half2_rn(acc[nt][0] + bv.x, acc[nt][1] + bv.y);
            *(__half2*)&g_xt[(size_t)na * COUT + col] = h;
        }
        int nb = na + 8;
        if (nb < N_NODES) {
            __half2 h = __floats2half2_rn(acc[nt][2] + bv.x, acc[nt][3] + bv.y);
            *(__half2*)&g_xt[(size_t)nb * COUT + col] = h;
        }
    }
}

// ---------------------------------------------------------------------------
// K_GATHER: warp-per-node. Segments 4-aligned -> one int4 index load per
// 4 edges, no tail. fp16 pair pre-add, fp32 accum, fused tanh.
__global__ void k_gather(float* __restrict__ out) {
    int gw   = (blockIdx.x * blockDim.x + threadIdx.x) >> 5;
    int lane = threadIdx.x & 31;
    if (gw >= N_NODES) return;

    int s = g_off[gw];
    int e = g_off[gw + 1];
    const uint2* xt2 = (const uint2*)g_xt;

    float4 accA = make_float4(0.f, 0.f, 0.f, 0.f);
    float4 accB = make_float4(0.f, 0.f, 0.f, 0.f);

    for (int i = s; i < e; i += 4) {
        int4 c = __ldg((const int4*)&g_scol[i]);
        uint2 r0 = __ldg(&xt2[(size_t)c.x * 32 + lane]);
        uint2 r1 = __ldg(&xt2[(size_t)c.y * 32 + lane]);
        uint2 r2 = __ldg(&xt2[(size_t)c.z * 32 + lane]);
        uint2 r3 = __ldg(&xt2[(size_t)c.w * 32 + lane]);
        __half2 pa0 = __hadd2(*(const __half2*)&r0.x, *(const __half2*)&r1.x);
        __half2 pa1 = __hadd2(*(const __half2*)&r0.y, *(const __half2*)&r1.y);
        __half2 pb0 = __hadd2(*(const __half2*)&r2.x, *(const __half2*)&r3.x);
        __half2 pb1 = __hadd2(*(const __half2*)&r2.y, *(const __half2*)&r3.y);
        float2 fa0 = __half22float2(pa0);
        float2 fa1 = __half22float2(pa1);
        float2 fb0 = __half22float2(pb0);
        float2 fb1 = __half22float2(pb1);
        accA.x += fa0.x; accA.y += fa0.y; accA.z += fa1.x; accA.w += fa1.y;
        accB.x += fb0.x; accB.y += fb0.y; accB.z += fb1.x; accB.w += fb1.y;
    }

    float4 r = make_float4(tanhf(accA.x + accB.x), tanhf(accA.y + accB.y),
                           tanhf(accA.z + accB.z), tanhf(accA.w + accB.w));
    ((float4*)out)[(size_t)gw * 32 + lane] = r;
}

// ---------------------------------------------------------------------------
extern "C" void kernel_launch(void* const* d_in, const int* in_sizes, int n_in,
                              void* d_out, int out_size) {
    const float* x  = (const float*)d_in[0];
    const void*  ei = d_in[1];
    const float* W  = (const float*)d_in[2];
    const float* b  = (const float*)d_in[3];
    float*       out = (float*)d_out;

    static cudaStream_t s1 = nullptr;
    static cudaEvent_t  evFork = nullptr, evJoin = nullptr;
    if (!s1) {
        cudaStreamCreateWithFlags(&s1, cudaStreamNonBlocking);
        cudaEventCreateWithFlags(&evFork, cudaEventDisableTiming);
        cudaEventCreateWithFlags(&evJoin, cudaEventDisableTiming);
        cudaFuncSetAttribute(k_linear, cudaFuncAttributeMaxDynamicSharedMemorySize,
                             (A_HALVES + 128 * LSTRIDE) * 2);
    }
    const int SMEM_LIN = (A_HALVES + 128 * LSTRIDE) * 2;   // 52.2 KB

    k_init<<<SCAN_BLOCKS, 256>>>(ei);                        // launch 1
    cudaEventRecord(evFork, 0);
    cudaStreamWaitEvent(s1, evFork, 0);

    // Side stream: CSR chain (count carries rank; scatter atomic-free).
    k_count<<<(N_EDGES + 255) / 256, 256, 0, s1>>>(ei);      // 2
    k_scanDL<<<SCAN_BLOCKS, 256, 0, s1>>>();                 // 3
    k_scatter<<<(N_EDGES + 255) / 256, 256, 0, s1>>>(ei);    // 4 (profiled)

    // Main stream: convert + linear (overlap CSR chain).
    k_xw<<<16 + (N_PAD * CIN / 4 + 255) / 256, 256>>>(x, W); // 5
    k_linear<<<(N_NODES + 63) / 64, 256, SMEM_LIN>>>(b);     // 6

    cudaEventRecord(evJoin, s1);
    cudaStreamWaitEvent(0, evJoin, 0);
    k_gather<<<(N_NODES * 32 + 255) / 256, 256>>>(out);      // 7
}